// round 4
// baseline (speedup 1.0000x reference)
#include <cuda_runtime.h>
#include <cuda_fp16.h>
#include <mma.h>
#include <math.h>
#include <stdint.h>

using namespace nvcuda;

#define N_NODES 100000
#define N_PAD   (N_NODES + 64)
#define N_EDGES 3200000
#define N_TOT   (N_EDGES + N_NODES)
#define F_IN    512
#define F_MID   256
#define F_OUT   64
#define K_STEPS 10

// ---------------- scratch ----------------
__device__ __half2 g_hh[(size_t)N_PAD * 32];       // h fp16 (unscaled)
__device__ __half2 g_y0[(size_t)N_PAD * 32];       // y = dinv*z ping
__device__ __half2 g_y1[(size_t)N_PAD * 32];       // pong
__device__ int     g_cnt[N_NODES];
__device__ int     g_off[N_NODES];
__device__ int     g_incl[N_NODES];
__device__ int     g_colptr[N_NODES + 1];
__device__ int     g_aux[128];
__device__ int     g_auxex[128];
__device__ float   g_dinv[N_NODES];
__device__ int     g_erow[N_TOT];

// ---------------- CSR build ----------------
__global__ void k_init() {
    int i = blockIdx.x * blockDim.x + threadIdx.x;
    if (i < N_NODES) { g_cnt[i] = 1; g_off[i] = 0; }
}
__global__ void k_count(const int* __restrict__ col) {
    int e = blockIdx.x * blockDim.x + threadIdx.x;
    if (e < N_EDGES) atomicAdd(&g_cnt[col[e]], 1);
}
__global__ void k_scan1() {   // also computes dinv
    __shared__ int s[1024];
    int i = blockIdx.x * 1024 + threadIdx.x;
    int v = (i < N_NODES) ? g_cnt[i] : 0;
    if (i < N_NODES) g_dinv[i] = rsqrtf((float)v);
    s[threadIdx.x] = v;
    __syncthreads();
    for (int d = 1; d < 1024; d <<= 1) {
        int t = (threadIdx.x >= d) ? s[threadIdx.x - d] : 0;
        __syncthreads();
        s[threadIdx.x] += t;
        __syncthreads();
    }
    if (i < N_NODES) g_incl[i] = s[threadIdx.x];
    if (threadIdx.x == 1023) g_aux[blockIdx.x] = s[1023];
}
__global__ void k_scanaux(int nb) {
    if (threadIdx.x == 0) {
        int run = 0;
        for (int b = 0; b < nb; b++) { g_auxex[b] = run; run += g_aux[b]; }
    }
}
__global__ void k_finalize() {
    int i = blockIdx.x * blockDim.x + threadIdx.x;
    if (i < N_NODES) {
        g_colptr[i + 1] = g_incl[i] + g_auxex[i >> 10];
        if (i == 0) g_colptr[0] = 0;
    }
}
__global__ void k_fill(const int* __restrict__ rowp, const int* __restrict__ colp) {
    int i = blockIdx.x * blockDim.x + threadIdx.x;
    if (i < N_TOT) {
        int r, c;
        if (i < N_EDGES) { r = rowp[i]; c = colp[i]; }
        else             { r = c = i - N_EDGES; }
        int idx = g_colptr[c] + atomicAdd(&g_off[c], 1);
        g_erow[idx] = r;
    }
}

// ---------------- fused MLP: h = relu(x@W1 + b1) @ W2 + b2 ; t never leaves smem ----------------
// 64 rows/block, 256 threads (8 warps). smem: ts[64][264] | union(Bs double / W2s / Cs) | As double.
#define TS_LD   264
#define TS_SZ   (64 * TS_LD)                 // 16896 floats
#define UN_OFF  TS_SZ
#define UN_SZ   (256 * 68)                   // 17408 floats (W2s is the largest user)
#define AS_OFF  (UN_OFF + UN_SZ)
#define AS_SZ   (2 * 64 * 20)                // 2560 floats
#define SMEM_FLOATS (AS_OFF + AS_SZ)         // 36864 floats = 147456 B

__global__ __launch_bounds__(256) void k_mlp(const float* __restrict__ A,
                                             const float* __restrict__ W1,
                                             const float* __restrict__ b1,
                                             const float* __restrict__ W2,
                                             const float* __restrict__ b2) {
    extern __shared__ float sm[];
    float* ts  = sm;                         // [64][264]
    float* un  = sm + UN_OFF;                // Bs: [2][16][264] / W2s: [256][68] / Cs: [64][68]
    float* Asb = sm + AS_OFF;                // [2][64][20]

    const int tid = threadIdx.x;
    const int warp = tid >> 5;
    const int wr = warp >> 2, wc = warp & 3;     // 2 x 4 warp grid
    const int m0 = blockIdx.x * 64;

    // ---------- phase 1: acc = x @ W1 (64 x 256), double-buffered ----------
    wmma::fragment<wmma::accumulator, 16, 16, 8, float> c1[2][4];
    #pragma unroll
    for (int i = 0; i < 2; i++)
        #pragma unroll
        for (int j = 0; j < 4; j++) wmma::fill_fragment(c1[i][j], 0.f);

    const int ar = tid >> 2, ac4 = (tid & 3) << 2;       // A tile coords (64x16)
    const int agr = min(m0 + ar, N_NODES - 1);
    float4 aR, bR[4];

    // prefetch k-tile 0
    aR = *(const float4*)&A[(size_t)agr * F_IN + ac4];
    #pragma unroll
    for (int l = 0; l < 4; l++) {
        int idx = tid + l * 256;
        int br = idx >> 6, bc4 = (idx & 63) << 2;
        bR[l] = *(const float4*)&W1[(size_t)br * F_MID + bc4];
    }
    {   // store buf 0 (tf32 convert)
        float4 v = aR;
        v.x = wmma::__float_to_tf32(v.x); v.y = wmma::__float_to_tf32(v.y);
        v.z = wmma::__float_to_tf32(v.z); v.w = wmma::__float_to_tf32(v.w);
        *(float4*)&Asb[ar * 20 + ac4] = v;
        #pragma unroll
        for (int l = 0; l < 4; l++) {
            int idx = tid + l * 256;
            int br = idx >> 6, bc4 = (idx & 63) << 2;
            float4 w = bR[l];
            w.x = wmma::__float_to_tf32(w.x); w.y = wmma::__float_to_tf32(w.y);
            w.z = wmma::__float_to_tf32(w.z); w.w = wmma::__float_to_tf32(w.w);
            *(float4*)&un[br * TS_LD + bc4] = w;
        }
    }
    __syncthreads();

    constexpr int NKT = F_IN / 16;   // 32
    for (int kt = 0; kt < NKT; kt++) {
        const int buf = kt & 1;
        if (kt + 1 < NKT) {          // prefetch next tile into regs
            const int k0 = (kt + 1) * 16;
            aR = *(const float4*)&A[(size_t)agr * F_IN + k0 + ac4];
            #pragma unroll
            for (int l = 0; l < 4; l++) {
                int idx = tid + l * 256;
                int br = idx >> 6, bc4 = (idx & 63) << 2;
                bR[l] = *(const float4*)&W1[(size_t)(k0 + br) * F_MID + bc4];
            }
        }
        float* As = Asb + buf * (64 * 20);
        float* Bs = un + buf * (16 * TS_LD);
        #pragma unroll
        for (int kk = 0; kk < 16; kk += 8) {
            wmma::fragment<wmma::matrix_a, 16, 16, 8, wmma::precision::tf32, wmma::row_major> a0, a1;
            wmma::load_matrix_sync(a0, &As[(wr * 32) * 20 + kk],      20);
            wmma::load_matrix_sync(a1, &As[(wr * 32 + 16) * 20 + kk], 20);
            #pragma unroll
            for (int j = 0; j < 4; j++) {
                wmma::fragment<wmma::matrix_b, 16, 16, 8, wmma::precision::tf32, wmma::row_major> b;
                wmma::load_matrix_sync(b, &Bs[kk * TS_LD + wc * 64 + j * 16], TS_LD);
                wmma::mma_sync(c1[0][j], a0, b, c1[0][j]);
                wmma::mma_sync(c1[1][j], a1, b, c1[1][j]);
            }
        }
        if (kt + 1 < NKT) {          // store prefetched tile to other buf
            const int nbuf = (kt + 1) & 1;
            float* Asn = Asb + nbuf * (64 * 20);
            float* Bsn = un + nbuf * (16 * TS_LD);
            float4 v = aR;
            v.x = wmma::__float_to_tf32(v.x); v.y = wmma::__float_to_tf32(v.y);
            v.z = wmma::__float_to_tf32(v.z); v.w = wmma::__float_to_tf32(v.w);
            *(float4*)&Asn[ar * 20 + ac4] = v;
            #pragma unroll
            for (int l = 0; l < 4; l++) {
                int idx = tid + l * 256;
                int br = idx >> 6, bc4 = (idx & 63) << 2;
                float4 w = bR[l];
                w.x = wmma::__float_to_tf32(w.x); w.y = wmma::__float_to_tf32(w.y);
                w.z = wmma::__float_to_tf32(w.z); w.w = wmma::__float_to_tf32(w.w);
                *(float4*)&Bsn[br * TS_LD + bc4] = w;
            }
        }
        __syncthreads();
    }

    // store phase-1 accumulators into ts
    #pragma unroll
    for (int i = 0; i < 2; i++)
        #pragma unroll
        for (int j = 0; j < 4; j++)
            wmma::store_matrix_sync(&ts[(wr * 32 + i * 16) * TS_LD + wc * 64 + j * 16],
                                    c1[i][j], TS_LD, wmma::mem_row_major);
    __syncthreads();

    // bias1 + relu + tf32 in place; concurrently stage W2 (tf32) into un
    #pragma unroll
    for (int l = 0; l < 16; l++) {
        int idx = tid + l * 256;                 // 4096 float4 over ts
        int r = idx >> 6, c4 = (idx & 63) << 2;
        float4 v = *(float4*)&ts[r * TS_LD + c4];
        float4 bb = *(const float4*)&b1[c4];
        v.x = wmma::__float_to_tf32(fmaxf(v.x + bb.x, 0.f));
        v.y = wmma::__float_to_tf32(fmaxf(v.y + bb.y, 0.f));
        v.z = wmma::__float_to_tf32(fmaxf(v.z + bb.z, 0.f));
        v.w = wmma::__float_to_tf32(fmaxf(v.w + bb.w, 0.f));
        *(float4*)&ts[r * TS_LD + c4] = v;
    }
    __syncthreads();
    #pragma unroll
    for (int l = 0; l < 16; l++) {
        int idx = tid + l * 256;                 // 4096 float4 over W2 (256x64)
        int r = idx >> 4, c4 = (idx & 15) << 2;
        float4 v = *(const float4*)&W2[(size_t)r * F_OUT + c4];
        v.x = wmma::__float_to_tf32(v.x); v.y = wmma::__float_to_tf32(v.y);
        v.z = wmma::__float_to_tf32(v.z); v.w = wmma::__float_to_tf32(v.w);
        *(float4*)&un[r * 68 + c4] = v;
    }
    __syncthreads();

    // ---------- phase 2: h = ts @ W2 (64 x 64) ----------
    wmma::fragment<wmma::accumulator, 16, 16, 8, float> c2[2];
    wmma::fill_fragment(c2[0], 0.f);
    wmma::fill_fragment(c2[1], 0.f);
    for (int k = 0; k < F_MID; k += 8) {
        wmma::fragment<wmma::matrix_a, 16, 16, 8, wmma::precision::tf32, wmma::row_major> a0, a1;
        wmma::fragment<wmma::matrix_b, 16, 16, 8, wmma::precision::tf32, wmma::row_major> b;
        wmma::load_matrix_sync(a0, &ts[(wr * 32) * TS_LD + k],      TS_LD);
        wmma::load_matrix_sync(a1, &ts[(wr * 32 + 16) * TS_LD + k], TS_LD);
        wmma::load_matrix_sync(b, &un[k * 68 + wc * 16], 68);
        wmma::mma_sync(c2[0], a0, b, c2[0]);
        wmma::mma_sync(c2[1], a1, b, c2[1]);
    }
    __syncthreads();    // W2s no longer needed; reuse un as Cs [64][68]
    wmma::store_matrix_sync(&un[(wr * 32) * 68 + wc * 16],      c2[0], 68, wmma::mem_row_major);
    wmma::store_matrix_sync(&un[(wr * 32 + 16) * 68 + wc * 16], c2[1], 68, wmma::mem_row_major);
    __syncthreads();

    #pragma unroll
    for (int l = 0; l < 4; l++) {                // 1024 float4 (64 x 16)
        int idx = tid + l * 256;
        int r = idx >> 4, c4 = (idx & 15) << 2;
        float4 v = *(float4*)&un[r * 68 + c4];
        float4 bb = *(const float4*)&b2[c4];
        v.x += bb.x; v.y += bb.y; v.z += bb.z; v.w += bb.w;
        int row = m0 + r;
        float di = (row < N_NODES) ? g_dinv[row] : 0.f;
        size_t oh = (size_t)row * 32 + (c4 >> 1);
        g_hh[oh]     = __floats2half2_rn(v.x, v.y);
        g_hh[oh + 1] = __floats2half2_rn(v.z, v.w);
        g_y0[oh]     = __floats2half2_rn(di * v.x, di * v.y);
        g_y0[oh + 1] = __floats2half2_rn(di * v.z, di * v.w);
    }
}

// ---------------- APPNP propagation ----------------
__device__ __forceinline__ void acc8(float2& a0, float2& a1, float2& a2, float2& a3,
                                     const __half2* __restrict__ zin, int r, int k) {
    float4 v = *(const float4*)&zin[(size_t)r * 32 + k * 4];
    const __half2* hp = (const __half2*)&v;
    float2 t0 = __half22float2(hp[0]);
    float2 t1 = __half22float2(hp[1]);
    float2 t2 = __half22float2(hp[2]);
    float2 t3 = __half22float2(hp[3]);
    a0.x += t0.x; a0.y += t0.y;
    a1.x += t1.x; a1.y += t1.y;
    a2.x += t2.x; a2.y += t2.y;
    a3.x += t3.x; a3.y += t3.y;
}

__global__ void k_prop(float* __restrict__ outF, int it) {
    const __half2* __restrict__ zin = (it & 1) ? g_y1 : g_y0;
    __half2* __restrict__ zout = (it & 1) ? g_y0 : g_y1;
    const int warp = threadIdx.x >> 5, lane = threadIdx.x & 31;
    const int node = blockIdx.x * 8 + warp;
    if (node >= N_NODES) return;
    const int g = lane >> 3, k = lane & 7;
    const int s = g_colptr[node], e = g_colptr[node + 1];

    float2 a0 = {0.f, 0.f}, a1 = {0.f, 0.f}, a2 = {0.f, 0.f}, a3 = {0.f, 0.f};
    int i = s + g;
    while (i + 12 < e) {                 // four independent 512B gathers in flight
        int r0 = g_erow[i];
        int r1 = g_erow[i + 4];
        int r2 = g_erow[i + 8];
        int r3 = g_erow[i + 12];
        acc8(a0, a1, a2, a3, zin, r0, k);
        acc8(a0, a1, a2, a3, zin, r1, k);
        acc8(a0, a1, a2, a3, zin, r2, k);
        acc8(a0, a1, a2, a3, zin, r3, k);
        i += 16;
    }
    while (i < e) {
        acc8(a0, a1, a2, a3, zin, g_erow[i], k);
        i += 4;
    }
    #pragma unroll
    for (int d = 8; d <= 16; d <<= 1) {
        a0.x += __shfl_xor_sync(0xffffffffu, a0.x, d);
        a0.y += __shfl_xor_sync(0xffffffffu, a0.y, d);
        a1.x += __shfl_xor_sync(0xffffffffu, a1.x, d);
        a1.y += __shfl_xor_sync(0xffffffffu, a1.y, d);
        a2.x += __shfl_xor_sync(0xffffffffu, a2.x, d);
        a2.y += __shfl_xor_sync(0xffffffffu, a2.y, d);
        a3.x += __shfl_xor_sync(0xffffffffu, a3.x, d);
        a3.y += __shfl_xor_sync(0xffffffffu, a3.y, d);
    }
    const float dc = g_dinv[node];
    float4 hv = *(const float4*)&g_hh[(size_t)node * 32 + k * 4];
    const __half2* hp = (const __half2*)&hv;
    float2 h0 = __half22float2(hp[0]), h1 = __half22float2(hp[1]);
    float2 h2 = __half22float2(hp[2]), h3 = __half22float2(hp[3]);
    const float w = 0.9f * dc;
    float z0x = w * a0.x + 0.1f * h0.x, z0y = w * a0.y + 0.1f * h0.y;
    float z1x = w * a1.x + 0.1f * h1.x, z1y = w * a1.y + 0.1f * h1.y;
    float z2x = w * a2.x + 0.1f * h2.x, z2y = w * a2.y + 0.1f * h2.y;
    float z3x = w * a3.x + 0.1f * h3.x, z3y = w * a3.y + 0.1f * h3.y;

    if (it != K_STEPS - 1) {
        if (g == 0) {
            __half2 o0 = __floats2half2_rn(dc * z0x, dc * z0y);
            __half2 o1 = __floats2half2_rn(dc * z1x, dc * z1y);
            __half2 o2 = __floats2half2_rn(dc * z2x, dc * z2y);
            __half2 o3 = __floats2half2_rn(dc * z3x, dc * z3y);
            uint4 pk;
            pk.x = *(unsigned*)&o0; pk.y = *(unsigned*)&o1;
            pk.z = *(unsigned*)&o2; pk.w = *(unsigned*)&o3;
            *(uint4*)&zout[(size_t)node * 32 + k * 4] = pk;
        }
    } else {
        float m = fmaxf(fmaxf(fmaxf(z0x, z0y), fmaxf(z1x, z1y)),
                        fmaxf(fmaxf(z2x, z2y), fmaxf(z3x, z3y)));
        #pragma unroll
        for (int d = 1; d <= 4; d <<= 1) m = fmaxf(m, __shfl_xor_sync(0xffffffffu, m, d));
        float sm = __expf(z0x - m) + __expf(z0y - m) + __expf(z1x - m) + __expf(z1y - m)
                 + __expf(z2x - m) + __expf(z2y - m) + __expf(z3x - m) + __expf(z3y - m);
        #pragma unroll
        for (int d = 1; d <= 4; d <<= 1) sm += __shfl_xor_sync(0xffffffffu, sm, d);
        float l = m + __logf(sm);
        if (g == 0) {
            float4 o;
            o.x = z0x - l; o.y = z0y - l; o.z = z1x - l; o.w = z1y - l;
            *(float4*)&outF[(size_t)node * F_OUT + k * 8] = o;
            o.x = z2x - l; o.y = z2y - l; o.z = z3x - l; o.w = z3y - l;
            *(float4*)&outF[(size_t)node * F_OUT + k * 8 + 4] = o;
        }
    }
}

// ---------------- launch ----------------
extern "C" void kernel_launch(void* const* d_in, const int* in_sizes, int n_in,
                              void* d_out, int out_size) {
    const float* x  = (const float*)d_in[0];
    const int*   ei = (const int*)d_in[1];
    const float* W1 = (const float*)d_in[2];
    const float* b1 = (const float*)d_in[3];
    const float* W2 = (const float*)d_in[4];
    const float* b2 = (const float*)d_in[5];
    float* out = (float*)d_out;

    const int* rowp = ei;
    const int* colp = ei + N_EDGES;

    // non-stream API, safe during capture; idempotent
    cudaFuncSetAttribute(k_mlp, cudaFuncAttributeMaxDynamicSharedMemorySize,
                         SMEM_FLOATS * (int)sizeof(float));

    k_init<<<(N_NODES + 255) / 256, 256>>>();
    k_count<<<(N_EDGES + 255) / 256, 256>>>(colp);
    int nb = (N_NODES + 1023) / 1024;
    k_scan1<<<nb, 1024>>>();
    k_scanaux<<<1, 32>>>(nb);
    k_finalize<<<(N_NODES + 255) / 256, 256>>>();
    k_fill<<<(N_TOT + 255) / 256, 256>>>(rowp, colp);

    int mb = (N_NODES + 63) / 64;     // 1563
    k_mlp<<<mb, 256, SMEM_FLOATS * sizeof(float)>>>(x, W1, b1, W2, b2);

    for (int it = 0; it < K_STEPS; ++it)
        k_prop<<<(N_NODES + 7) / 8, 256>>>(out, it);
}

// round 5
// speedup vs baseline: 1.2034x; 1.2034x over previous
#include <cuda_runtime.h>
#include <cuda_fp16.h>
#include <mma.h>
#include <math.h>
#include <stdint.h>

using namespace nvcuda;

#define N_NODES 100000
#define N_PAD   (N_NODES + 64)
#define N_EDGES 3200000
#define N_TOT   (N_EDGES + N_NODES)
#define F_IN    512
#define F_MID   256
#define F_OUT   64
#define K_STEPS 10

// ---------------- scratch ----------------
__device__ float   g_t[(size_t)N_PAD * F_MID];     // x@W1 (pre-bias/relu)
__device__ __half2 g_hh[(size_t)N_PAD * 32];       // h fp16 (unscaled)
__device__ __half2 g_y0[(size_t)N_PAD * 32];       // y = dinv*z ping
__device__ __half2 g_y1[(size_t)N_PAD * 32];       // pong
__device__ int     g_cnt[N_NODES];
__device__ int     g_off[N_NODES];
__device__ int     g_incl[N_NODES];
__device__ int     g_colptr[N_NODES + 1];
__device__ int     g_aux[128];
__device__ int     g_auxex[128];
__device__ float   g_dinv[N_NODES];
__device__ int     g_erow[N_TOT];

// ---------------- CSR build ----------------
__global__ void k_init() {
    int i = blockIdx.x * blockDim.x + threadIdx.x;
    if (i < N_NODES) { g_cnt[i] = 1; g_off[i] = 0; }
}
__global__ void k_count(const int* __restrict__ col) {
    int e = blockIdx.x * blockDim.x + threadIdx.x;
    if (e < N_EDGES) atomicAdd(&g_cnt[col[e]], 1);
}
__global__ void k_scan1() {   // block-level inclusive scan; also computes dinv
    __shared__ int s[1024];
    int i = blockIdx.x * 1024 + threadIdx.x;
    int v = (i < N_NODES) ? g_cnt[i] : 0;
    if (i < N_NODES) g_dinv[i] = rsqrtf((float)v);
    s[threadIdx.x] = v;
    __syncthreads();
    for (int d = 1; d < 1024; d <<= 1) {
        int t = (threadIdx.x >= d) ? s[threadIdx.x - d] : 0;
        __syncthreads();
        s[threadIdx.x] += t;
        __syncthreads();
    }
    if (i < N_NODES) g_incl[i] = s[threadIdx.x];
    if (threadIdx.x == 1023) g_aux[blockIdx.x] = s[1023];
}
__global__ void k_scanaux(int nb) {      // parallel 128-wide exclusive scan
    __shared__ int s[128];
    int v = (threadIdx.x < nb) ? g_aux[threadIdx.x] : 0;
    s[threadIdx.x] = v;
    __syncthreads();
    for (int d = 1; d < 128; d <<= 1) {
        int t = (threadIdx.x >= d) ? s[threadIdx.x - d] : 0;
        __syncthreads();
        s[threadIdx.x] += t;
        __syncthreads();
    }
    if (threadIdx.x < nb) g_auxex[threadIdx.x] = s[threadIdx.x] - v;  // exclusive
}
__global__ void k_finalize() {
    int i = blockIdx.x * blockDim.x + threadIdx.x;
    if (i < N_NODES) {
        g_colptr[i + 1] = g_incl[i] + g_auxex[i >> 10];
        if (i == 0) g_colptr[0] = 0;
    }
}
__global__ void k_fill(const int* __restrict__ rowp, const int* __restrict__ colp) {
    int i = blockIdx.x * blockDim.x + threadIdx.x;
    if (i < N_TOT) {
        int r, c;
        if (i < N_EDGES) { r = rowp[i]; c = colp[i]; }
        else             { r = c = i - N_EDGES; }
        int idx = g_colptr[c] + atomicAdd(&g_off[c], 1);
        g_erow[idx] = r;
    }
}

// ---------------- GEMM1: g_t = x @ W1 (TF32; conversion at smem fill) ----------------
__global__ void k_gemm1(const float* __restrict__ A, const float* __restrict__ B) {
    constexpr int BM = 64, BN = 128, BK = 16;
    __shared__ float As[BM][BK + 4];
    __shared__ float Bs[BK][BN + 4];
    const int tid = threadIdx.x;        // 256
    const int warp = tid >> 5;
    const int wr = warp >> 2, wc = warp & 3;
    const int m0 = blockIdx.x * BM, n0 = blockIdx.y * BN;

    wmma::fragment<wmma::accumulator, 16, 16, 8, float> c[2][2];
    #pragma unroll
    for (int i = 0; i < 2; i++)
        #pragma unroll
        for (int j = 0; j < 2; j++) wmma::fill_fragment(c[i][j], 0.f);

    for (int k0 = 0; k0 < F_IN; k0 += BK) {
        {
            int r = tid >> 2, c4 = (tid & 3) << 2;
            int gr = min(m0 + r, N_NODES - 1);
            float4 v = *(const float4*)&A[(size_t)gr * F_IN + k0 + c4];
            v.x = wmma::__float_to_tf32(v.x); v.y = wmma::__float_to_tf32(v.y);
            v.z = wmma::__float_to_tf32(v.z); v.w = wmma::__float_to_tf32(v.w);
            *(float4*)&As[r][c4] = v;
        }
        #pragma unroll
        for (int l = 0; l < 2; l++) {
            int idx = tid + l * 256;
            int br = idx >> 5, bc4 = (idx & 31) << 2;
            float4 v = *(const float4*)&B[(size_t)(k0 + br) * F_MID + n0 + bc4];
            v.x = wmma::__float_to_tf32(v.x); v.y = wmma::__float_to_tf32(v.y);
            v.z = wmma::__float_to_tf32(v.z); v.w = wmma::__float_to_tf32(v.w);
            *(float4*)&Bs[br][bc4] = v;
        }
        __syncthreads();
        #pragma unroll
        for (int kk = 0; kk < BK; kk += 8) {
            wmma::fragment<wmma::matrix_a, 16, 16, 8, wmma::precision::tf32, wmma::row_major> a0, a1;
            wmma::fragment<wmma::matrix_b, 16, 16, 8, wmma::precision::tf32, wmma::row_major> b0, b1;
            wmma::load_matrix_sync(a0, &As[wr * 32][kk],      BK + 4);
            wmma::load_matrix_sync(a1, &As[wr * 32 + 16][kk], BK + 4);
            wmma::load_matrix_sync(b0, &Bs[kk][wc * 32],      BN + 4);
            wmma::load_matrix_sync(b1, &Bs[kk][wc * 32 + 16], BN + 4);
            wmma::mma_sync(c[0][0], a0, b0, c[0][0]);
            wmma::mma_sync(c[0][1], a0, b1, c[0][1]);
            wmma::mma_sync(c[1][0], a1, b0, c[1][0]);
            wmma::mma_sync(c[1][1], a1, b1, c[1][1]);
        }
        __syncthreads();
    }
    #pragma unroll
    for (int i = 0; i < 2; i++)
        #pragma unroll
        for (int j = 0; j < 2; j++)
            wmma::store_matrix_sync(
                &g_t[(size_t)(m0 + wr * 32 + i * 16) * F_MID + n0 + wc * 32 + j * 16],
                c[i][j], F_MID, wmma::mem_row_major);
}

// ---------------- GEMM2: h = relu(t+b1) @ W2 + b2 ; writes fp16 h only ----------------
__global__ void k_gemm2(const float* __restrict__ B,
                        const float* __restrict__ b1, const float* __restrict__ b2) {
    constexpr int BM = 64, BN = 64, BK = 16;
    __shared__ float As[BM][BK + 4];
    __shared__ float Bs[BK][BN + 4];
    __shared__ float Cs[BM][BN + 4];
    const int tid = threadIdx.x;        // 128
    const int warp = tid >> 5;
    const int wr = warp >> 1, wc = warp & 1;
    const int m0 = blockIdx.x * BM;

    wmma::fragment<wmma::accumulator, 16, 16, 8, float> c[2][2];
    #pragma unroll
    for (int i = 0; i < 2; i++)
        #pragma unroll
        for (int j = 0; j < 2; j++) wmma::fill_fragment(c[i][j], 0.f);

    for (int k0 = 0; k0 < F_MID; k0 += BK) {
        #pragma unroll
        for (int l = 0; l < 2; l++) {
            int idx = tid + l * 128;
            int r = idx >> 2, c4 = (idx & 3) << 2;
            float4 v = *(const float4*)&g_t[(size_t)(m0 + r) * F_MID + k0 + c4];
            float4 bb = *(const float4*)&b1[k0 + c4];
            v.x = wmma::__float_to_tf32(fmaxf(v.x + bb.x, 0.f));
            v.y = wmma::__float_to_tf32(fmaxf(v.y + bb.y, 0.f));
            v.z = wmma::__float_to_tf32(fmaxf(v.z + bb.z, 0.f));
            v.w = wmma::__float_to_tf32(fmaxf(v.w + bb.w, 0.f));
            *(float4*)&As[r][c4] = v;
        }
        #pragma unroll
        for (int l = 0; l < 2; l++) {
            int idx = tid + l * 128;
            int br = idx >> 4, bc4 = (idx & 15) << 2;
            float4 v = *(const float4*)&B[(size_t)(k0 + br) * F_OUT + bc4];
            v.x = wmma::__float_to_tf32(v.x); v.y = wmma::__float_to_tf32(v.y);
            v.z = wmma::__float_to_tf32(v.z); v.w = wmma::__float_to_tf32(v.w);
            *(float4*)&Bs[br][bc4] = v;
        }
        __syncthreads();
        #pragma unroll
        for (int kk = 0; kk < BK; kk += 8) {
            wmma::fragment<wmma::matrix_a, 16, 16, 8, wmma::precision::tf32, wmma::row_major> a0, a1;
            wmma::fragment<wmma::matrix_b, 16, 16, 8, wmma::precision::tf32, wmma::row_major> b0, b1f;
            wmma::load_matrix_sync(a0, &As[wr * 32][kk],      BK + 4);
            wmma::load_matrix_sync(a1, &As[wr * 32 + 16][kk], BK + 4);
            wmma::load_matrix_sync(b0, &Bs[kk][wc * 32],      BN + 4);
            wmma::load_matrix_sync(b1f, &Bs[kk][wc * 32 + 16], BN + 4);
            wmma::mma_sync(c[0][0], a0, b0,  c[0][0]);
            wmma::mma_sync(c[0][1], a0, b1f, c[0][1]);
            wmma::mma_sync(c[1][0], a1, b0,  c[1][0]);
            wmma::mma_sync(c[1][1], a1, b1f, c[1][1]);
        }
        __syncthreads();
    }
    #pragma unroll
    for (int i = 0; i < 2; i++)
        #pragma unroll
        for (int j = 0; j < 2; j++)
            wmma::store_matrix_sync(&Cs[wr * 32 + i * 16][wc * 32 + j * 16],
                                    c[i][j], BN + 4, wmma::mem_row_major);
    __syncthreads();
    #pragma unroll
    for (int l = 0; l < 8; l++) {
        int idx = tid + l * 128;
        int r = idx >> 4, c4 = (idx & 15) << 2;
        float4 v = *(float4*)&Cs[r][c4];
        float4 bb = *(const float4*)&b2[c4];
        v.x += bb.x; v.y += bb.y; v.z += bb.z; v.w += bb.w;
        size_t oh = (size_t)(m0 + r) * 32 + (c4 >> 1);
        g_hh[oh]     = __floats2half2_rn(v.x, v.y);
        g_hh[oh + 1] = __floats2half2_rn(v.z, v.w);
    }
}

// ---------------- y0 = dinv * h (join point of CSR and MLP chains) ----------------
__global__ void k_scale() {
    int i = blockIdx.x * blockDim.x + threadIdx.x;   // one thread = 8 features
    if (i >= N_NODES * 8) return;
    int node = i >> 3, q = i & 7;
    float di = g_dinv[node];
    float4 v = *(const float4*)&g_hh[(size_t)node * 32 + q * 4];
    const __half2* hp = (const __half2*)&v;
    __half2 o[4];
    #pragma unroll
    for (int j = 0; j < 4; j++) {
        float2 f = __half22float2(hp[j]);
        o[j] = __floats2half2_rn(di * f.x, di * f.y);
    }
    *(float4*)&g_y0[(size_t)node * 32 + q * 4] = *(float4*)o;
}

// ---------------- APPNP propagation ----------------
__device__ __forceinline__ void acc8(float2& a0, float2& a1, float2& a2, float2& a3,
                                     const __half2* __restrict__ zin, int r, int k) {
    float4 v = *(const float4*)&zin[(size_t)r * 32 + k * 4];
    const __half2* hp = (const __half2*)&v;
    float2 t0 = __half22float2(hp[0]);
    float2 t1 = __half22float2(hp[1]);
    float2 t2 = __half22float2(hp[2]);
    float2 t3 = __half22float2(hp[3]);
    a0.x += t0.x; a0.y += t0.y;
    a1.x += t1.x; a1.y += t1.y;
    a2.x += t2.x; a2.y += t2.y;
    a3.x += t3.x; a3.y += t3.y;
}

__global__ void k_prop(float* __restrict__ outF, int it) {
    const __half2* __restrict__ zin = (it & 1) ? g_y1 : g_y0;
    __half2* __restrict__ zout = (it & 1) ? g_y0 : g_y1;
    const int warp = threadIdx.x >> 5, lane = threadIdx.x & 31;
    const int node = blockIdx.x * 8 + warp;
    if (node >= N_NODES) return;
    const int g = lane >> 3, k = lane & 7;
    const int s = g_colptr[node], e = g_colptr[node + 1];

    float2 a0 = {0.f, 0.f}, a1 = {0.f, 0.f}, a2 = {0.f, 0.f}, a3 = {0.f, 0.f};
    int i = s + g;
    while (i + 12 < e) {                 // four independent 512B gathers in flight
        int r0 = g_erow[i];
        int r1 = g_erow[i + 4];
        int r2 = g_erow[i + 8];
        int r3 = g_erow[i + 12];
        acc8(a0, a1, a2, a3, zin, r0, k);
        acc8(a0, a1, a2, a3, zin, r1, k);
        acc8(a0, a1, a2, a3, zin, r2, k);
        acc8(a0, a1, a2, a3, zin, r3, k);
        i += 16;
    }
    while (i < e) {
        acc8(a0, a1, a2, a3, zin, g_erow[i], k);
        i += 4;
    }
    #pragma unroll
    for (int d = 8; d <= 16; d <<= 1) {
        a0.x += __shfl_xor_sync(0xffffffffu, a0.x, d);
        a0.y += __shfl_xor_sync(0xffffffffu, a0.y, d);
        a1.x += __shfl_xor_sync(0xffffffffu, a1.x, d);
        a1.y += __shfl_xor_sync(0xffffffffu, a1.y, d);
        a2.x += __shfl_xor_sync(0xffffffffu, a2.x, d);
        a2.y += __shfl_xor_sync(0xffffffffu, a2.y, d);
        a3.x += __shfl_xor_sync(0xffffffffu, a3.x, d);
        a3.y += __shfl_xor_sync(0xffffffffu, a3.y, d);
    }
    const float dc = g_dinv[node];
    float4 hv = *(const float4*)&g_hh[(size_t)node * 32 + k * 4];
    const __half2* hp = (const __half2*)&hv;
    float2 h0 = __half22float2(hp[0]), h1 = __half22float2(hp[1]);
    float2 h2 = __half22float2(hp[2]), h3 = __half22float2(hp[3]);
    const float w = 0.9f * dc;
    float z0x = w * a0.x + 0.1f * h0.x, z0y = w * a0.y + 0.1f * h0.y;
    float z1x = w * a1.x + 0.1f * h1.x, z1y = w * a1.y + 0.1f * h1.y;
    float z2x = w * a2.x + 0.1f * h2.x, z2y = w * a2.y + 0.1f * h2.y;
    float z3x = w * a3.x + 0.1f * h3.x, z3y = w * a3.y + 0.1f * h3.y;

    if (it != K_STEPS - 1) {
        if (g == 0) {
            __half2 o0 = __floats2half2_rn(dc * z0x, dc * z0y);
            __half2 o1 = __floats2half2_rn(dc * z1x, dc * z1y);
            __half2 o2 = __floats2half2_rn(dc * z2x, dc * z2y);
            __half2 o3 = __floats2half2_rn(dc * z3x, dc * z3y);
            uint4 pk;
            pk.x = *(unsigned*)&o0; pk.y = *(unsigned*)&o1;
            pk.z = *(unsigned*)&o2; pk.w = *(unsigned*)&o3;
            *(uint4*)&zout[(size_t)node * 32 + k * 4] = pk;
        }
    } else {
        float m = fmaxf(fmaxf(fmaxf(z0x, z0y), fmaxf(z1x, z1y)),
                        fmaxf(fmaxf(z2x, z2y), fmaxf(z3x, z3y)));
        #pragma unroll
        for (int d = 1; d <= 4; d <<= 1) m = fmaxf(m, __shfl_xor_sync(0xffffffffu, m, d));
        float sm = __expf(z0x - m) + __expf(z0y - m) + __expf(z1x - m) + __expf(z1y - m)
                 + __expf(z2x - m) + __expf(z2y - m) + __expf(z3x - m) + __expf(z3y - m);
        #pragma unroll
        for (int d = 1; d <= 4; d <<= 1) sm += __shfl_xor_sync(0xffffffffu, sm, d);
        float l = m + __logf(sm);
        if (g == 0) {
            float4 o;
            o.x = z0x - l; o.y = z0y - l; o.z = z1x - l; o.w = z1y - l;
            *(float4*)&outF[(size_t)node * F_OUT + k * 8] = o;
            o.x = z2x - l; o.y = z2y - l; o.z = z3x - l; o.w = z3y - l;
            *(float4*)&outF[(size_t)node * F_OUT + k * 8 + 4] = o;
        }
    }
}

// ---------------- launch ----------------
extern "C" void kernel_launch(void* const* d_in, const int* in_sizes, int n_in,
                              void* d_out, int out_size) {
    const float* x  = (const float*)d_in[0];
    const int*   ei = (const int*)d_in[1];
    const float* W1 = (const float*)d_in[2];
    const float* b1 = (const float*)d_in[3];
    const float* W2 = (const float*)d_in[4];
    const float* b2 = (const float*)d_in[5];
    float* out = (float*)d_out;

    const int* rowp = ei;
    const int* colp = ei + N_EDGES;

    // one-time handle creation (host resources only; happens on the first,
    // non-captured correctness call and is reused identically thereafter)
    static cudaStream_t s_side = nullptr;
    static cudaEvent_t  s_ev0 = nullptr, s_ev1 = nullptr;
    if (!s_side) {
        cudaStreamCreateWithFlags(&s_side, cudaStreamNonBlocking);
        cudaEventCreateWithFlags(&s_ev0, cudaEventDisableTiming);
        cudaEventCreateWithFlags(&s_ev1, cudaEventDisableTiming);
    }

    // fork: CSR build on side stream, MLP on main stream
    cudaEventRecord(s_ev0, 0);
    cudaStreamWaitEvent(s_side, s_ev0, 0);

    k_init<<<(N_NODES + 255) / 256, 256, 0, s_side>>>();
    k_count<<<(N_EDGES + 255) / 256, 256, 0, s_side>>>(colp);
    int nb = (N_NODES + 1023) / 1024;
    k_scan1<<<nb, 1024, 0, s_side>>>();
    k_scanaux<<<1, 128, 0, s_side>>>(nb);
    k_finalize<<<(N_NODES + 255) / 256, 256, 0, s_side>>>();
    k_fill<<<(N_TOT + 255) / 256, 256, 0, s_side>>>(rowp, colp);
    cudaEventRecord(s_ev1, s_side);

    int mb = (N_NODES + 63) / 64;     // 1563
    k_gemm1<<<dim3(mb, F_MID / 128), 256>>>(x, W1);
    k_gemm2<<<dim3(mb, 1), 128>>>(W2, b1, b2);

    // join: prop needs both chains
    cudaStreamWaitEvent(0, s_ev1, 0);
    k_scale<<<(N_NODES * 8 + 255) / 256, 256>>>();

    for (int it = 0; it < K_STEPS; ++it)
        k_prop<<<(N_NODES + 7) / 8, 256>>>(out, it);
}

// round 6
// speedup vs baseline: 1.3971x; 1.1610x over previous
#include <cuda_runtime.h>
#include <cuda_fp16.h>
#include <cuda_bf16.h>
#include <mma.h>
#include <math.h>
#include <stdint.h>

using namespace nvcuda;

#define N_NODES 100000
#define N_PAD   (N_NODES + 64)
#define N_EDGES 3200000
#define N_TOT   (N_EDGES + N_NODES)
#define F_IN    512
#define F_MID   256
#define F_OUT   64
#define K_STEPS 10

// ---------------- scratch ----------------
__device__ float   g_t[(size_t)N_PAD * F_MID];     // x@W1 (fp32, pre-bias/relu)
__device__ __half2 g_hh[(size_t)N_PAD * 32];       // h fp16 (unscaled)
__device__ __half2 g_y0[(size_t)N_PAD * 32];       // y = dinv*z ping
__device__ __half2 g_y1[(size_t)N_PAD * 32];       // pong
__device__ int     g_cnt[N_NODES];
__device__ int     g_off[N_NODES];
__device__ int     g_incl[N_NODES];
__device__ int     g_colptr[N_NODES + 1];
__device__ int     g_aux[128];
__device__ int     g_auxex[128];
__device__ float   g_dinv[N_NODES];
__device__ int     g_erow[N_TOT];

// ---------------- helpers ----------------
__device__ __forceinline__ uint4 pack8_bf16(float4 v0, float4 v1) {
    __nv_bfloat162 p0 = __floats2bfloat162_rn(v0.x, v0.y);
    __nv_bfloat162 p1 = __floats2bfloat162_rn(v0.z, v0.w);
    __nv_bfloat162 p2 = __floats2bfloat162_rn(v1.x, v1.y);
    __nv_bfloat162 p3 = __floats2bfloat162_rn(v1.z, v1.w);
    uint4 u;
    u.x = *(unsigned*)&p0; u.y = *(unsigned*)&p1;
    u.z = *(unsigned*)&p2; u.w = *(unsigned*)&p3;
    return u;
}

// ---------------- CSR build ----------------
__global__ void k_init() {
    int i = blockIdx.x * blockDim.x + threadIdx.x;
    if (i < N_NODES) { g_cnt[i] = 1; g_off[i] = 0; }
}
__global__ void k_count(const int* __restrict__ col) {
    int e = blockIdx.x * blockDim.x + threadIdx.x;
    if (e < N_EDGES) atomicAdd(&g_cnt[col[e]], 1);
}
__global__ void k_scan1() {   // block inclusive scan + dinv
    __shared__ int s[1024];
    int i = blockIdx.x * 1024 + threadIdx.x;
    int v = (i < N_NODES) ? g_cnt[i] : 0;
    if (i < N_NODES) g_dinv[i] = rsqrtf((float)v);
    s[threadIdx.x] = v;
    __syncthreads();
    for (int d = 1; d < 1024; d <<= 1) {
        int t = (threadIdx.x >= d) ? s[threadIdx.x - d] : 0;
        __syncthreads();
        s[threadIdx.x] += t;
        __syncthreads();
    }
    if (i < N_NODES) g_incl[i] = s[threadIdx.x];
    if (threadIdx.x == 1023) g_aux[blockIdx.x] = s[1023];
}
__global__ void k_scanaux(int nb) {      // 128-wide exclusive scan
    __shared__ int s[128];
    int v = (threadIdx.x < nb) ? g_aux[threadIdx.x] : 0;
    s[threadIdx.x] = v;
    __syncthreads();
    for (int d = 1; d < 128; d <<= 1) {
        int t = (threadIdx.x >= d) ? s[threadIdx.x - d] : 0;
        __syncthreads();
        s[threadIdx.x] += t;
        __syncthreads();
    }
    if (threadIdx.x < nb) g_auxex[threadIdx.x] = s[threadIdx.x] - v;
}
__global__ void k_finalize() {
    int i = blockIdx.x * blockDim.x + threadIdx.x;
    if (i < N_NODES) {
        g_colptr[i + 1] = g_incl[i] + g_auxex[i >> 10];
        if (i == 0) g_colptr[0] = 0;
    }
}
__global__ void k_fill(const int* __restrict__ rowp, const int* __restrict__ colp) {
    int i = blockIdx.x * blockDim.x + threadIdx.x;
    if (i < N_TOT) {
        int r, c;
        if (i < N_EDGES) { r = rowp[i]; c = colp[i]; }
        else             { r = c = i - N_EDGES; }
        int idx = g_colptr[c] + atomicAdd(&g_off[c], 1);
        g_erow[idx] = r;
    }
}

// ---------------- GEMM1: g_t = x @ W1 (bf16 inputs, fp32 accum) ----------------
// BM=64, BN=128, BK=32, 256 threads (2x4 warps, 32x32 warp tiles), m16n16k16.
#define A1_LD 48
#define B1_LD 144
__global__ __launch_bounds__(256) void k_gemm1(const float* __restrict__ A,
                                               const float* __restrict__ B) {
    __shared__ __nv_bfloat16 As[64][A1_LD];
    __shared__ __nv_bfloat16 Bs[32][B1_LD];
    const int tid = threadIdx.x;
    const int warp = tid >> 5;
    const int wr = warp >> 2, wc = warp & 3;
    const int m0 = blockIdx.x * 64, n0 = blockIdx.y * 128;

    wmma::fragment<wmma::accumulator, 16, 16, 16, float> c[2][2];
    #pragma unroll
    for (int i = 0; i < 2; i++)
        #pragma unroll
        for (int j = 0; j < 2; j++) wmma::fill_fragment(c[i][j], 0.f);

    const int ar = tid >> 2, ac8 = (tid & 3) << 3;            // A: 64 rows x 4 col-groups
    const int agr = min(m0 + ar, N_NODES - 1);

    for (int k0 = 0; k0 < F_IN; k0 += 32) {
        {   // A tile 64x32: 8 bf16 per thread
            float4 v0 = *(const float4*)&A[(size_t)agr * F_IN + k0 + ac8];
            float4 v1 = *(const float4*)&A[(size_t)agr * F_IN + k0 + ac8 + 4];
            *(uint4*)&As[ar][ac8] = pack8_bf16(v0, v1);
        }
        #pragma unroll
        for (int l = 0; l < 2; l++) {   // B tile 32x128: 16 bf16 per thread
            int idx = tid + l * 256;
            int br = idx >> 4, bc8 = (idx & 15) << 3;
            float4 v0 = *(const float4*)&B[(size_t)(k0 + br) * F_MID + n0 + bc8];
            float4 v1 = *(const float4*)&B[(size_t)(k0 + br) * F_MID + n0 + bc8 + 4];
            *(uint4*)&Bs[br][bc8] = pack8_bf16(v0, v1);
        }
        __syncthreads();
        #pragma unroll
        for (int kk = 0; kk < 32; kk += 16) {
            wmma::fragment<wmma::matrix_a, 16, 16, 16, __nv_bfloat16, wmma::row_major> a0, a1;
            wmma::fragment<wmma::matrix_b, 16, 16, 16, __nv_bfloat16, wmma::row_major> b0, b1;
            wmma::load_matrix_sync(a0, &As[wr * 32][kk],      A1_LD);
            wmma::load_matrix_sync(a1, &As[wr * 32 + 16][kk], A1_LD);
            wmma::load_matrix_sync(b0, &Bs[kk][wc * 32],      B1_LD);
            wmma::load_matrix_sync(b1, &Bs[kk][wc * 32 + 16], B1_LD);
            wmma::mma_sync(c[0][0], a0, b0, c[0][0]);
            wmma::mma_sync(c[0][1], a0, b1, c[0][1]);
            wmma::mma_sync(c[1][0], a1, b0, c[1][0]);
            wmma::mma_sync(c[1][1], a1, b1, c[1][1]);
        }
        __syncthreads();
    }
    #pragma unroll
    for (int i = 0; i < 2; i++)
        #pragma unroll
        for (int j = 0; j < 2; j++)
            wmma::store_matrix_sync(
                &g_t[(size_t)(m0 + wr * 32 + i * 16) * F_MID + n0 + wc * 32 + j * 16],
                c[i][j], F_MID, wmma::mem_row_major);
}

// ---------------- GEMM2: h = relu(t+b1) @ W2 + b2 (bf16 inputs) ----------------
// BM=64, BN=64, BK=32, 128 threads (2x2 warps, 32x32 warp tiles).
#define A2_LD 48
#define B2_LD 80
__global__ __launch_bounds__(128) void k_gemm2(const float* __restrict__ B,
                                               const float* __restrict__ b1,
                                               const float* __restrict__ b2) {
    __shared__ __nv_bfloat16 As[64][A2_LD];
    __shared__ __nv_bfloat16 Bs[32][B2_LD];
    __shared__ float Cs[64][68];
    const int tid = threadIdx.x;
    const int warp = tid >> 5;
    const int wr = warp >> 1, wc = warp & 1;
    const int m0 = blockIdx.x * 64;

    wmma::fragment<wmma::accumulator, 16, 16, 16, float> c[2][2];
    #pragma unroll
    for (int i = 0; i < 2; i++)
        #pragma unroll
        for (int j = 0; j < 2; j++) wmma::fill_fragment(c[i][j], 0.f);

    for (int k0 = 0; k0 < F_MID; k0 += 32) {
        #pragma unroll
        for (int l = 0; l < 2; l++) {   // A tile 64x32: relu(t+b1) -> bf16
            int idx = tid + l * 128;
            int r = idx >> 2, c8 = (idx & 3) << 3;
            float4 v0 = *(const float4*)&g_t[(size_t)(m0 + r) * F_MID + k0 + c8];
            float4 v1 = *(const float4*)&g_t[(size_t)(m0 + r) * F_MID + k0 + c8 + 4];
            float4 u0 = *(const float4*)&b1[k0 + c8];
            float4 u1 = *(const float4*)&b1[k0 + c8 + 4];
            v0.x = fmaxf(v0.x + u0.x, 0.f); v0.y = fmaxf(v0.y + u0.y, 0.f);
            v0.z = fmaxf(v0.z + u0.z, 0.f); v0.w = fmaxf(v0.w + u0.w, 0.f);
            v1.x = fmaxf(v1.x + u1.x, 0.f); v1.y = fmaxf(v1.y + u1.y, 0.f);
            v1.z = fmaxf(v1.z + u1.z, 0.f); v1.w = fmaxf(v1.w + u1.w, 0.f);
            *(uint4*)&As[r][c8] = pack8_bf16(v0, v1);
        }
        #pragma unroll
        for (int l = 0; l < 2; l++) {   // B tile 32x64
            int idx = tid + l * 128;
            int br = idx >> 3, bc8 = (idx & 7) << 3;
            float4 v0 = *(const float4*)&B[(size_t)(k0 + br) * F_OUT + bc8];
            float4 v1 = *(const float4*)&B[(size_t)(k0 + br) * F_OUT + bc8 + 4];
            *(uint4*)&Bs[br][bc8] = pack8_bf16(v0, v1);
        }
        __syncthreads();
        #pragma unroll
        for (int kk = 0; kk < 32; kk += 16) {
            wmma::fragment<wmma::matrix_a, 16, 16, 16, __nv_bfloat16, wmma::row_major> a0, a1;
            wmma::fragment<wmma::matrix_b, 16, 16, 16, __nv_bfloat16, wmma::row_major> b0, b1f;
            wmma::load_matrix_sync(a0, &As[wr * 32][kk],      A2_LD);
            wmma::load_matrix_sync(a1, &As[wr * 32 + 16][kk], A2_LD);
            wmma::load_matrix_sync(b0, &Bs[kk][wc * 32],      B2_LD);
            wmma::load_matrix_sync(b1f, &Bs[kk][wc * 32 + 16], B2_LD);
            wmma::mma_sync(c[0][0], a0, b0,  c[0][0]);
            wmma::mma_sync(c[0][1], a0, b1f, c[0][1]);
            wmma::mma_sync(c[1][0], a1, b0,  c[1][0]);
            wmma::mma_sync(c[1][1], a1, b1f, c[1][1]);
        }
        __syncthreads();
    }
    #pragma unroll
    for (int i = 0; i < 2; i++)
        #pragma unroll
        for (int j = 0; j < 2; j++)
            wmma::store_matrix_sync(&Cs[wr * 32 + i * 16][wc * 32 + j * 16],
                                    c[i][j], 68, wmma::mem_row_major);
    __syncthreads();
    #pragma unroll
    for (int l = 0; l < 8; l++) {
        int idx = tid + l * 128;
        int r = idx >> 4, c4 = (idx & 15) << 2;
        float4 v = *(float4*)&Cs[r][c4];
        float4 bb = *(const float4*)&b2[c4];
        v.x += bb.x; v.y += bb.y; v.z += bb.z; v.w += bb.w;
        int row = m0 + r;
        float di = (row < N_NODES) ? g_dinv[row] : 0.f;
        size_t oh = (size_t)row * 32 + (c4 >> 1);
        g_hh[oh]     = __floats2half2_rn(v.x, v.y);
        g_hh[oh + 1] = __floats2half2_rn(v.z, v.w);
        g_y0[oh]     = __floats2half2_rn(di * v.x, di * v.y);
        g_y0[oh + 1] = __floats2half2_rn(di * v.z, di * v.w);
    }
}

// ---------------- APPNP propagation ----------------
__device__ __forceinline__ void acc8(float2& a0, float2& a1, float2& a2, float2& a3,
                                     const __half2* __restrict__ zin, int r, int k) {
    float4 v = *(const float4*)&zin[(size_t)r * 32 + k * 4];
    const __half2* hp = (const __half2*)&v;
    float2 t0 = __half22float2(hp[0]);
    float2 t1 = __half22float2(hp[1]);
    float2 t2 = __half22float2(hp[2]);
    float2 t3 = __half22float2(hp[3]);
    a0.x += t0.x; a0.y += t0.y;
    a1.x += t1.x; a1.y += t1.y;
    a2.x += t2.x; a2.y += t2.y;
    a3.x += t3.x; a3.y += t3.y;
}

__global__ void k_prop(float* __restrict__ outF, int it) {
    const __half2* __restrict__ zin = (it & 1) ? g_y1 : g_y0;
    __half2* __restrict__ zout = (it & 1) ? g_y0 : g_y1;
    const int warp = threadIdx.x >> 5, lane = threadIdx.x & 31;
    const int node = blockIdx.x * 8 + warp;
    if (node >= N_NODES) return;
    const int g = lane >> 3, k = lane & 7;
    const int s = g_colptr[node], e = g_colptr[node + 1];

    float2 a0 = {0.f, 0.f}, a1 = {0.f, 0.f}, a2 = {0.f, 0.f}, a3 = {0.f, 0.f};
    int i = s + g;
    while (i + 12 < e) {                 // four independent 512B gathers in flight
        int r0 = g_erow[i];
        int r1 = g_erow[i + 4];
        int r2 = g_erow[i + 8];
        int r3 = g_erow[i + 12];
        acc8(a0, a1, a2, a3, zin, r0, k);
        acc8(a0, a1, a2, a3, zin, r1, k);
        acc8(a0, a1, a2, a3, zin, r2, k);
        acc8(a0, a1, a2, a3, zin, r3, k);
        i += 16;
    }
    while (i < e) {
        acc8(a0, a1, a2, a3, zin, g_erow[i], k);
        i += 4;
    }
    #pragma unroll
    for (int d = 8; d <= 16; d <<= 1) {
        a0.x += __shfl_xor_sync(0xffffffffu, a0.x, d);
        a0.y += __shfl_xor_sync(0xffffffffu, a0.y, d);
        a1.x += __shfl_xor_sync(0xffffffffu, a1.x, d);
        a1.y += __shfl_xor_sync(0xffffffffu, a1.y, d);
        a2.x += __shfl_xor_sync(0xffffffffu, a2.x, d);
        a2.y += __shfl_xor_sync(0xffffffffu, a2.y, d);
        a3.x += __shfl_xor_sync(0xffffffffu, a3.x, d);
        a3.y += __shfl_xor_sync(0xffffffffu, a3.y, d);
    }
    const float dc = g_dinv[node];
    float4 hv = *(const float4*)&g_hh[(size_t)node * 32 + k * 4];
    const __half2* hp = (const __half2*)&hv;
    float2 h0 = __half22float2(hp[0]), h1 = __half22float2(hp[1]);
    float2 h2 = __half22float2(hp[2]), h3 = __half22float2(hp[3]);
    const float w = 0.9f * dc;
    float z0x = w * a0.x + 0.1f * h0.x, z0y = w * a0.y + 0.1f * h0.y;
    float z1x = w * a1.x + 0.1f * h1.x, z1y = w * a1.y + 0.1f * h1.y;
    float z2x = w * a2.x + 0.1f * h2.x, z2y = w * a2.y + 0.1f * h2.y;
    float z3x = w * a3.x + 0.1f * h3.x, z3y = w * a3.y + 0.1f * h3.y;

    if (it != K_STEPS - 1) {
        if (g == 0) {
            __half2 o0 = __floats2half2_rn(dc * z0x, dc * z0y);
            __half2 o1 = __floats2half2_rn(dc * z1x, dc * z1y);
            __half2 o2 = __floats2half2_rn(dc * z2x, dc * z2y);
            __half2 o3 = __floats2half2_rn(dc * z3x, dc * z3y);
            uint4 pk;
            pk.x = *(unsigned*)&o0; pk.y = *(unsigned*)&o1;
            pk.z = *(unsigned*)&o2; pk.w = *(unsigned*)&o3;
            *(uint4*)&zout[(size_t)node * 32 + k * 4] = pk;
        }
    } else {
        float m = fmaxf(fmaxf(fmaxf(z0x, z0y), fmaxf(z1x, z1y)),
                        fmaxf(fmaxf(z2x, z2y), fmaxf(z3x, z3y)));
        #pragma unroll
        for (int d = 1; d <= 4; d <<= 1) m = fmaxf(m, __shfl_xor_sync(0xffffffffu, m, d));
        float sm = __expf(z0x - m) + __expf(z0y - m) + __expf(z1x - m) + __expf(z1y - m)
                 + __expf(z2x - m) + __expf(z2y - m) + __expf(z3x - m) + __expf(z3y - m);
        #pragma unroll
        for (int d = 1; d <= 4; d <<= 1) sm += __shfl_xor_sync(0xffffffffu, sm, d);
        float l = m + __logf(sm);
        if (g == 0) {
            float4 o;
            o.x = z0x - l; o.y = z0y - l; o.z = z1x - l; o.w = z1y - l;
            *(float4*)&outF[(size_t)node * F_OUT + k * 8] = o;
            o.x = z2x - l; o.y = z2y - l; o.z = z3x - l; o.w = z3y - l;
            *(float4*)&outF[(size_t)node * F_OUT + k * 8 + 4] = o;
        }
    }
}

// ---------------- launch ----------------
extern "C" void kernel_launch(void* const* d_in, const int* in_sizes, int n_in,
                              void* d_out, int out_size) {
    const float* x  = (const float*)d_in[0];
    const int*   ei = (const int*)d_in[1];
    const float* W1 = (const float*)d_in[2];
    const float* b1 = (const float*)d_in[3];
    const float* W2 = (const float*)d_in[4];
    const float* b2 = (const float*)d_in[5];
    float* out = (float*)d_out;

    const int* rowp = ei;
    const int* colp = ei + N_EDGES;

    // CSR-by-destination build
    k_init<<<(N_NODES + 255) / 256, 256>>>();
    k_count<<<(N_EDGES + 255) / 256, 256>>>(colp);
    int nb = (N_NODES + 1023) / 1024;
    k_scan1<<<nb, 1024>>>();
    k_scanaux<<<1, 128>>>(nb);
    k_finalize<<<(N_NODES + 255) / 256, 256>>>();
    k_fill<<<(N_TOT + 255) / 256, 256>>>(rowp, colp);

    // MLP (bf16 tensor cores, fp32 accumulate)
    int mb = (N_NODES + 63) / 64;     // 1563
    k_gemm1<<<dim3(mb, F_MID / 128), 256>>>(x, W1);
    k_gemm2<<<dim3(mb, 1), 128>>>(W2, b1, b2);

    // K propagation steps
    for (int it = 0; it < K_STEPS; ++it)
        k_prop<<<(N_NODES + 7) / 8, 256>>>(out, it);
}

// round 7
// speedup vs baseline: 1.4807x; 1.0598x over previous
#include <cuda_runtime.h>
#include <cuda_fp16.h>
#include <cuda_bf16.h>
#include <mma.h>
#include <math.h>
#include <stdint.h>

using namespace nvcuda;

#define N_NODES 100000
#define N_PAD   (N_NODES + 64)
#define N_EDGES 3200000
#define N_TOT   (N_EDGES + N_NODES)
#define F_IN    512
#define F_MID   256
#define F_OUT   64
#define K_STEPS 10

// ---------------- scratch ----------------
__device__ float   g_t[(size_t)N_PAD * F_MID];     // x@W1 (fp32, pre-bias/relu)
__device__ __half2 g_hh[(size_t)N_PAD * 32];       // h fp16 (unscaled)
__device__ __half2 g_y0[(size_t)N_PAD * 32];       // y = dinv*z ping
__device__ __half2 g_y1[(size_t)N_PAD * 32];       // pong
__device__ int     g_cnt[N_NODES];
__device__ int     g_off[N_NODES];
__device__ int     g_incl[N_NODES];
__device__ int     g_colptr[N_NODES + 1];
__device__ int     g_aux[128];
__device__ int     g_auxex[128];
__device__ float   g_dinv[N_NODES];
__device__ int     g_erow[N_TOT];

// ---------------- helpers ----------------
__device__ __forceinline__ uint4 pack8_bf16(float4 v0, float4 v1) {
    __nv_bfloat162 p0 = __floats2bfloat162_rn(v0.x, v0.y);
    __nv_bfloat162 p1 = __floats2bfloat162_rn(v0.z, v0.w);
    __nv_bfloat162 p2 = __floats2bfloat162_rn(v1.x, v1.y);
    __nv_bfloat162 p3 = __floats2bfloat162_rn(v1.z, v1.w);
    uint4 u;
    u.x = *(unsigned*)&p0; u.y = *(unsigned*)&p1;
    u.z = *(unsigned*)&p2; u.w = *(unsigned*)&p3;
    return u;
}

// ---------------- CSR build ----------------
__global__ void k_init() {
    int i = blockIdx.x * blockDim.x + threadIdx.x;
    if (i < N_NODES) { g_cnt[i] = 1; g_off[i] = 0; }
}
__global__ void k_count(const int* __restrict__ col) {
    int e = blockIdx.x * blockDim.x + threadIdx.x;
    if (e < N_EDGES) atomicAdd(&g_cnt[col[e]], 1);
}
__global__ void k_scan1() {   // block inclusive scan + dinv
    __shared__ int s[1024];
    int i = blockIdx.x * 1024 + threadIdx.x;
    int v = (i < N_NODES) ? g_cnt[i] : 0;
    if (i < N_NODES) g_dinv[i] = rsqrtf((float)v);
    s[threadIdx.x] = v;
    __syncthreads();
    for (int d = 1; d < 1024; d <<= 1) {
        int t = (threadIdx.x >= d) ? s[threadIdx.x - d] : 0;
        __syncthreads();
        s[threadIdx.x] += t;
        __syncthreads();
    }
    if (i < N_NODES) g_incl[i] = s[threadIdx.x];
    if (threadIdx.x == 1023) g_aux[blockIdx.x] = s[1023];
}
__global__ void k_scanaux(int nb) {      // 128-wide exclusive scan
    __shared__ int s[128];
    int v = (threadIdx.x < nb) ? g_aux[threadIdx.x] : 0;
    s[threadIdx.x] = v;
    __syncthreads();
    for (int d = 1; d < 128; d <<= 1) {
        int t = (threadIdx.x >= d) ? s[threadIdx.x - d] : 0;
        __syncthreads();
        s[threadIdx.x] += t;
        __syncthreads();
    }
    if (threadIdx.x < nb) g_auxex[threadIdx.x] = s[threadIdx.x] - v;
}
__global__ void k_finalize() {
    int i = blockIdx.x * blockDim.x + threadIdx.x;
    if (i < N_NODES) {
        g_colptr[i + 1] = g_incl[i] + g_auxex[i >> 10];
        if (i == 0) g_colptr[0] = 0;
    }
}
__global__ void k_fill(const int* __restrict__ rowp, const int* __restrict__ colp) {
    int i = blockIdx.x * blockDim.x + threadIdx.x;
    if (i < N_TOT) {
        int r, c;
        if (i < N_EDGES) { r = rowp[i]; c = colp[i]; }
        else             { r = c = i - N_EDGES; }
        int idx = g_colptr[c] + atomicAdd(&g_off[c], 1);
        g_erow[idx] = r;
    }
}

// ---------------- GEMM1: g_t = x @ W1 (bf16 in, fp32 accum; BN = full 256) ----------------
// BM=64, BN=256, BK=32, 256 threads, 2x4 warp grid, warp tile 32x64 (c[2][4]).
#define A1_LD 40
#define B1_LD 264
__global__ __launch_bounds__(256) void k_gemm1(const float* __restrict__ A,
                                               const float* __restrict__ B) {
    __shared__ __nv_bfloat16 As[64][A1_LD];
    __shared__ __nv_bfloat16 Bs[32][B1_LD];
    const int tid = threadIdx.x;
    const int warp = tid >> 5;
    const int wr = warp >> 2, wc = warp & 3;
    const int m0 = blockIdx.x * 64;

    wmma::fragment<wmma::accumulator, 16, 16, 16, float> c[2][4];
    #pragma unroll
    for (int i = 0; i < 2; i++)
        #pragma unroll
        for (int j = 0; j < 4; j++) wmma::fill_fragment(c[i][j], 0.f);

    const int ar = tid >> 2, ac8 = (tid & 3) << 3;   // A: 64 rows x 4 groups of 8
    const int agr = min(m0 + ar, N_NODES - 1);

    for (int k0 = 0; k0 < F_IN; k0 += 32) {
        {   // A tile 64x32: 8 bf16 per thread
            float4 v0 = *(const float4*)&A[(size_t)agr * F_IN + k0 + ac8];
            float4 v1 = *(const float4*)&A[(size_t)agr * F_IN + k0 + ac8 + 4];
            *(uint4*)&As[ar][ac8] = pack8_bf16(v0, v1);
        }
        #pragma unroll
        for (int l = 0; l < 4; l++) {   // B tile 32x256: 32 bf16 per thread
            int idx = tid + l * 256;
            int br = idx >> 5, bc8 = (idx & 31) << 3;
            float4 v0 = *(const float4*)&B[(size_t)(k0 + br) * F_MID + bc8];
            float4 v1 = *(const float4*)&B[(size_t)(k0 + br) * F_MID + bc8 + 4];
            *(uint4*)&Bs[br][bc8] = pack8_bf16(v0, v1);
        }
        __syncthreads();
        #pragma unroll
        for (int kk = 0; kk < 32; kk += 16) {
            wmma::fragment<wmma::matrix_a, 16, 16, 16, __nv_bfloat16, wmma::row_major> a0, a1;
            wmma::load_matrix_sync(a0, &As[wr * 32][kk],      A1_LD);
            wmma::load_matrix_sync(a1, &As[wr * 32 + 16][kk], A1_LD);
            #pragma unroll
            for (int j = 0; j < 4; j++) {
                wmma::fragment<wmma::matrix_b, 16, 16, 16, __nv_bfloat16, wmma::row_major> b;
                wmma::load_matrix_sync(b, &Bs[kk][wc * 64 + j * 16], B1_LD);
                wmma::mma_sync(c[0][j], a0, b, c[0][j]);
                wmma::mma_sync(c[1][j], a1, b, c[1][j]);
            }
        }
        __syncthreads();
    }
    #pragma unroll
    for (int i = 0; i < 2; i++)
        #pragma unroll
        for (int j = 0; j < 4; j++)
            wmma::store_matrix_sync(
                &g_t[(size_t)(m0 + wr * 32 + i * 16) * F_MID + wc * 64 + j * 16],
                c[i][j], F_MID, wmma::mem_row_major);
}

// ---------------- GEMM2: h = relu(t+b1) @ W2 + b2 (bf16 inputs) ----------------
#define A2_LD 48
#define B2_LD 80
__global__ __launch_bounds__(128) void k_gemm2(const float* __restrict__ B,
                                               const float* __restrict__ b1,
                                               const float* __restrict__ b2) {
    __shared__ __nv_bfloat16 As[64][A2_LD];
    __shared__ __nv_bfloat16 Bs[32][B2_LD];
    __shared__ float Cs[64][68];
    const int tid = threadIdx.x;
    const int warp = tid >> 5;
    const int wr = warp >> 1, wc = warp & 1;
    const int m0 = blockIdx.x * 64;

    wmma::fragment<wmma::accumulator, 16, 16, 16, float> c[2][2];
    #pragma unroll
    for (int i = 0; i < 2; i++)
        #pragma unroll
        for (int j = 0; j < 2; j++) wmma::fill_fragment(c[i][j], 0.f);

    for (int k0 = 0; k0 < F_MID; k0 += 32) {
        #pragma unroll
        for (int l = 0; l < 2; l++) {   // A tile 64x32: relu(t+b1) -> bf16
            int idx = tid + l * 128;
            int r = idx >> 2, c8 = (idx & 3) << 3;
            float4 v0 = *(const float4*)&g_t[(size_t)(m0 + r) * F_MID + k0 + c8];
            float4 v1 = *(const float4*)&g_t[(size_t)(m0 + r) * F_MID + k0 + c8 + 4];
            float4 u0 = *(const float4*)&b1[k0 + c8];
            float4 u1 = *(const float4*)&b1[k0 + c8 + 4];
            v0.x = fmaxf(v0.x + u0.x, 0.f); v0.y = fmaxf(v0.y + u0.y, 0.f);
            v0.z = fmaxf(v0.z + u0.z, 0.f); v0.w = fmaxf(v0.w + u0.w, 0.f);
            v1.x = fmaxf(v1.x + u1.x, 0.f); v1.y = fmaxf(v1.y + u1.y, 0.f);
            v1.z = fmaxf(v1.z + u1.z, 0.f); v1.w = fmaxf(v1.w + u1.w, 0.f);
            *(uint4*)&As[r][c8] = pack8_bf16(v0, v1);
        }
        #pragma unroll
        for (int l = 0; l < 2; l++) {   // B tile 32x64
            int idx = tid + l * 128;
            int br = idx >> 3, bc8 = (idx & 7) << 3;
            float4 v0 = *(const float4*)&B[(size_t)(k0 + br) * F_OUT + bc8];
            float4 v1 = *(const float4*)&B[(size_t)(k0 + br) * F_OUT + bc8 + 4];
            *(uint4*)&Bs[br][bc8] = pack8_bf16(v0, v1);
        }
        __syncthreads();
        #pragma unroll
        for (int kk = 0; kk < 32; kk += 16) {
            wmma::fragment<wmma::matrix_a, 16, 16, 16, __nv_bfloat16, wmma::row_major> a0, a1;
            wmma::fragment<wmma::matrix_b, 16, 16, 16, __nv_bfloat16, wmma::row_major> b0, b1f;
            wmma::load_matrix_sync(a0, &As[wr * 32][kk],      A2_LD);
            wmma::load_matrix_sync(a1, &As[wr * 32 + 16][kk], A2_LD);
            wmma::load_matrix_sync(b0, &Bs[kk][wc * 32],      B2_LD);
            wmma::load_matrix_sync(b1f, &Bs[kk][wc * 32 + 16], B2_LD);
            wmma::mma_sync(c[0][0], a0, b0,  c[0][0]);
            wmma::mma_sync(c[0][1], a0, b1f, c[0][1]);
            wmma::mma_sync(c[1][0], a1, b0,  c[1][0]);
            wmma::mma_sync(c[1][1], a1, b1f, c[1][1]);
        }
        __syncthreads();
    }
    #pragma unroll
    for (int i = 0; i < 2; i++)
        #pragma unroll
        for (int j = 0; j < 2; j++)
            wmma::store_matrix_sync(&Cs[wr * 32 + i * 16][wc * 32 + j * 16],
                                    c[i][j], 68, wmma::mem_row_major);
    __syncthreads();
    #pragma unroll
    for (int l = 0; l < 8; l++) {
        int idx = tid + l * 128;
        int r = idx >> 4, c4 = (idx & 15) << 2;
        float4 v = *(float4*)&Cs[r][c4];
        float4 bb = *(const float4*)&b2[c4];
        v.x += bb.x; v.y += bb.y; v.z += bb.z; v.w += bb.w;
        int row = m0 + r;
        float di = (row < N_NODES) ? g_dinv[row] : 0.f;
        size_t oh = (size_t)row * 32 + (c4 >> 1);
        g_hh[oh]     = __floats2half2_rn(v.x, v.y);
        g_hh[oh + 1] = __floats2half2_rn(v.z, v.w);
        g_y0[oh]     = __floats2half2_rn(di * v.x, di * v.y);
        g_y0[oh + 1] = __floats2half2_rn(di * v.z, di * v.w);
    }
}

// ---------------- APPNP propagation ----------------
__device__ __forceinline__ void acc8(float2& a0, float2& a1, float2& a2, float2& a3,
                                     const __half2* __restrict__ zin, int r, int k) {
    float4 v = *(const float4*)&zin[(size_t)r * 32 + k * 4];
    const __half2* hp = (const __half2*)&v;
    float2 t0 = __half22float2(hp[0]);
    float2 t1 = __half22float2(hp[1]);
    float2 t2 = __half22float2(hp[2]);
    float2 t3 = __half22float2(hp[3]);
    a0.x += t0.x; a0.y += t0.y;
    a1.x += t1.x; a1.y += t1.y;
    a2.x += t2.x; a2.y += t2.y;
    a3.x += t3.x; a3.y += t3.y;
}

__global__ void k_prop(float* __restrict__ outF, int it) {
    const __half2* __restrict__ zin = (it & 1) ? g_y1 : g_y0;
    __half2* __restrict__ zout = (it & 1) ? g_y0 : g_y1;
    const int warp = threadIdx.x >> 5, lane = threadIdx.x & 31;
    const int node = blockIdx.x * 8 + warp;
    if (node >= N_NODES) return;
    const int g = lane >> 3, k = lane & 7;
    const int s = g_colptr[node], e = g_colptr[node + 1];

    float2 a0 = {0.f, 0.f}, a1 = {0.f, 0.f}, a2 = {0.f, 0.f}, a3 = {0.f, 0.f};
    int i = s + g;
    while (i + 12 < e) {                 // four independent 512B gathers in flight
        int r0 = g_erow[i];
        int r1 = g_erow[i + 4];
        int r2 = g_erow[i + 8];
        int r3 = g_erow[i + 12];
        acc8(a0, a1, a2, a3, zin, r0, k);
        acc8(a0, a1, a2, a3, zin, r1, k);
        acc8(a0, a1, a2, a3, zin, r2, k);
        acc8(a0, a1, a2, a3, zin, r3, k);
        i += 16;
    }
    while (i < e) {
        acc8(a0, a1, a2, a3, zin, g_erow[i], k);
        i += 4;
    }
    #pragma unroll
    for (int d = 8; d <= 16; d <<= 1) {
        a0.x += __shfl_xor_sync(0xffffffffu, a0.x, d);
        a0.y += __shfl_xor_sync(0xffffffffu, a0.y, d);
        a1.x += __shfl_xor_sync(0xffffffffu, a1.x, d);
        a1.y += __shfl_xor_sync(0xffffffffu, a1.y, d);
        a2.x += __shfl_xor_sync(0xffffffffu, a2.x, d);
        a2.y += __shfl_xor_sync(0xffffffffu, a2.y, d);
        a3.x += __shfl_xor_sync(0xffffffffu, a3.x, d);
        a3.y += __shfl_xor_sync(0xffffffffu, a3.y, d);
    }
    const float dc = g_dinv[node];
    float4 hv = *(const float4*)&g_hh[(size_t)node * 32 + k * 4];
    const __half2* hp = (const __half2*)&hv;
    float2 h0 = __half22float2(hp[0]), h1 = __half22float2(hp[1]);
    float2 h2 = __half22float2(hp[2]), h3 = __half22float2(hp[3]);
    const float w = 0.9f * dc;
    float z0x = w * a0.x + 0.1f * h0.x, z0y = w * a0.y + 0.1f * h0.y;
    float z1x = w * a1.x + 0.1f * h1.x, z1y = w * a1.y + 0.1f * h1.y;
    float z2x = w * a2.x + 0.1f * h2.x, z2y = w * a2.y + 0.1f * h2.y;
    float z3x = w * a3.x + 0.1f * h3.x, z3y = w * a3.y + 0.1f * h3.y;

    if (it != K_STEPS - 1) {
        if (g == 0) {
            __half2 o0 = __floats2half2_rn(dc * z0x, dc * z0y);
            __half2 o1 = __floats2half2_rn(dc * z1x, dc * z1y);
            __half2 o2 = __floats2half2_rn(dc * z2x, dc * z2y);
            __half2 o3 = __floats2half2_rn(dc * z3x, dc * z3y);
            uint4 pk;
            pk.x = *(unsigned*)&o0; pk.y = *(unsigned*)&o1;
            pk.z = *(unsigned*)&o2; pk.w = *(unsigned*)&o3;
            *(uint4*)&zout[(size_t)node * 32 + k * 4] = pk;
        }
    } else {
        float m = fmaxf(fmaxf(fmaxf(z0x, z0y), fmaxf(z1x, z1y)),
                        fmaxf(fmaxf(z2x, z2y), fmaxf(z3x, z3y)));
        #pragma unroll
        for (int d = 1; d <= 4; d <<= 1) m = fmaxf(m, __shfl_xor_sync(0xffffffffu, m, d));
        float sm = __expf(z0x - m) + __expf(z0y - m) + __expf(z1x - m) + __expf(z1y - m)
                 + __expf(z2x - m) + __expf(z2y - m) + __expf(z3x - m) + __expf(z3y - m);
        #pragma unroll
        for (int d = 1; d <= 4; d <<= 1) sm += __shfl_xor_sync(0xffffffffu, sm, d);
        float l = m + __logf(sm);
        if (g == 0) {
            float4 o;
            o.x = z0x - l; o.y = z0y - l; o.z = z1x - l; o.w = z1y - l;
            *(float4*)&outF[(size_t)node * F_OUT + k * 8] = o;
            o.x = z2x - l; o.y = z2y - l; o.z = z3x - l; o.w = z3y - l;
            *(float4*)&outF[(size_t)node * F_OUT + k * 8 + 4] = o;
        }
    }
}

// ---------------- launch ----------------
extern "C" void kernel_launch(void* const* d_in, const int* in_sizes, int n_in,
                              void* d_out, int out_size) {
    const float* x  = (const float*)d_in[0];
    const int*   ei = (const int*)d_in[1];
    const float* W1 = (const float*)d_in[2];
    const float* b1 = (const float*)d_in[3];
    const float* W2 = (const float*)d_in[4];
    const float* b2 = (const float*)d_in[5];
    float* out = (float*)d_out;

    const int* rowp = ei;
    const int* colp = ei + N_EDGES;

    // CSR-by-destination build
    k_init<<<(N_NODES + 255) / 256, 256>>>();
    k_count<<<(N_EDGES + 255) / 256, 256>>>(colp);
    int nb = (N_NODES + 1023) / 1024;
    k_scan1<<<nb, 1024>>>();
    k_scanaux<<<1, 128>>>(nb);
    k_finalize<<<(N_NODES + 255) / 256, 256>>>();
    k_fill<<<(N_TOT + 255) / 256, 256>>>(rowp, colp);

    // MLP (bf16 tensor cores, fp32 accumulate)
    int mb = (N_NODES + 63) / 64;     // 1563
    k_gemm1<<<mb, 256>>>(x, W1);
    k_gemm2<<<mb, 128>>>(W2, b1, b2);

    // K propagation steps
    for (int it = 0; it < K_STEPS; ++it)
        k_prop<<<(N_NODES + 7) / 8, 256>>>(out, it);
}